// round 1
// baseline (speedup 1.0000x reference)
#include <cuda_runtime.h>
#include <cuda_bf16.h>
#include <math.h>

// ---------------- problem constants ----------------
#define T_TOK   2048
#define HID     2048
#define NH      16
#define D_NOPE  128
#define D_ROPE  64
#define D_QK    192           // 128 + 64
#define D_V     128
#define Q_LORA  1536
#define KV_LORA 512
#define QKV_A_N 2112          // Q_LORA + KV_LORA + D_ROPE
#define SCALING 0.07216878364870322f   // 192^-0.5

// ---------------- scratch (device globals, no allocation) ----------------
__device__ __align__(128) float g_qkv_a [T_TOK * QKV_A_N];       // 2048 x 2112
__device__ __align__(128) float g_qn    [T_TOK * Q_LORA];        // 2048 x 1536
__device__ __align__(128) float g_kvn   [T_TOK * KV_LORA];       // 2048 x 512
__device__ __align__(128) float g_qbuf  [T_TOK * NH * D_QK];     // 2048 x 3072
__device__ __align__(128) float g_kvbuf [T_TOK * NH * 256];      // 2048 x 4096
__device__ __align__(128) float g_kpe   [T_TOK * D_ROPE];        // 2048 x 64
__device__ __align__(128) float g_attn  [T_TOK * NH * D_V];      // 2048 x 2048

// ---------------- generic fp32 SGEMM: C[M,N] = A[M,K] @ B[K,N] ----------------
// BM=128, BN=64, BK=8, 256 threads, 8x4 per-thread micro-tile.
// Requires M%128==0, N%64==0, K%8==0 (true for all 4 GEMMs here).
__global__ __launch_bounds__(256) void sgemm_kernel(
    const float* __restrict__ A, const float* __restrict__ B,
    float* __restrict__ C, int M, int N, int K)
{
    __shared__ float As[8][128];
    __shared__ float Bs[8][64];

    const int tid  = threadIdx.x;
    const int row0 = blockIdx.y * 128;
    const int col0 = blockIdx.x * 64;
    const int tr   = (tid >> 4) << 3;   // 0..120
    const int tc   = (tid & 15) << 2;   // 0..60

    const int am = tid >> 1;            // 0..127
    const int ak = (tid & 1) << 2;      // 0 or 4
    const int bk = tid >> 5;            // 0..7
    const int bn = (tid & 31) << 1;     // 0..62

    float acc[8][4];
#pragma unroll
    for (int i = 0; i < 8; i++)
#pragma unroll
        for (int j = 0; j < 4; j++) acc[i][j] = 0.f;

    const float* Aptr = A + (size_t)(row0 + am) * K + ak;
    const float* Bptr = B + (size_t)bk * N + col0 + bn;

    for (int k0 = 0; k0 < K; k0 += 8) {
        float4 av = *(const float4*)(Aptr + k0);
        float2 bv = *(const float2*)(Bptr + (size_t)k0 * N);
        As[ak + 0][am] = av.x;
        As[ak + 1][am] = av.y;
        As[ak + 2][am] = av.z;
        As[ak + 3][am] = av.w;
        Bs[bk][bn]     = bv.x;
        Bs[bk][bn + 1] = bv.y;
        __syncthreads();
#pragma unroll
        for (int k = 0; k < 8; k++) {
            float a[8], b[4];
#pragma unroll
            for (int i = 0; i < 8; i++) a[i] = As[k][tr + i];
#pragma unroll
            for (int j = 0; j < 4; j++) b[j] = Bs[k][tc + j];
#pragma unroll
            for (int i = 0; i < 8; i++)
#pragma unroll
                for (int j = 0; j < 4; j++) acc[i][j] += a[i] * b[j];
        }
        __syncthreads();
    }

#pragma unroll
    for (int i = 0; i < 8; i++) {
        float4 o = make_float4(acc[i][0], acc[i][1], acc[i][2], acc[i][3]);
        *(float4*)(C + (size_t)(row0 + tr + i) * N + col0 + tc) = o;
    }
}

// ---------------- RMSNorm: out[row, :] = x * rsqrt(mean(x^2)+eps) * gamma ----------------
__global__ __launch_bounds__(256) void rmsnorm_kernel(
    const float* __restrict__ in, int ld, int off, int width,
    const float* __restrict__ gamma, float* __restrict__ out)
{
    const int row = blockIdx.x;
    const float* x = in + (size_t)row * ld + off;
    float ss = 0.f;
    for (int i = threadIdx.x; i < width; i += 256) {
        float v = x[i];
        ss += v * v;
    }
#pragma unroll
    for (int o = 16; o; o >>= 1) ss += __shfl_xor_sync(0xffffffffu, ss, o);
    __shared__ float warp_s[8];
    __shared__ float s_inv;
    if ((threadIdx.x & 31) == 0) warp_s[threadIdx.x >> 5] = ss;
    __syncthreads();
    if (threadIdx.x == 0) {
        float t = 0.f;
#pragma unroll
        for (int i = 0; i < 8; i++) t += warp_s[i];
        s_inv = rsqrtf(t / (float)width + 1e-6f);
    }
    __syncthreads();
    const float inv = s_inv;
    float* o = out + (size_t)row * width;
    for (int i = threadIdx.x; i < width; i += 256)
        o[i] = x[i] * inv * gamma[i];
}

// ---------------- RoPE (interleaved pairs) on q_pe (in-place) and k_pe ----------------
__global__ __launch_bounds__(256) void rope_kernel(
    float* __restrict__ q, const float* __restrict__ qkv_a,
    float* __restrict__ kpe, const int* __restrict__ positions)
{
    const int t = blockIdx.x;
    const float pos = (float)positions[t];
    for (int i = threadIdx.x; i < NH * 32 + 32; i += 256) {
        if (i < NH * 32) {
            const int h = i >> 5, p = i & 31;
            const float inv = powf(10000.0f, -(float)p / 32.0f);
            float s, c;
            sincosf(pos * inv, &s, &c);
            float* base = q + (size_t)t * (NH * D_QK) + h * D_QK + D_NOPE;
            const float x1 = base[2 * p], x2 = base[2 * p + 1];
            base[2 * p]     = x1 * c - x2 * s;
            base[2 * p + 1] = x1 * s + x2 * c;
        } else {
            const int p = i - NH * 32;
            const float inv = powf(10000.0f, -(float)p / 32.0f);
            float s, c;
            sincosf(pos * inv, &s, &c);
            const float* src = qkv_a + (size_t)t * QKV_A_N + (Q_LORA + KV_LORA);
            const float x1 = src[2 * p], x2 = src[2 * p + 1];
            kpe[(size_t)t * D_ROPE + 2 * p]     = x1 * c - x2 * s;
            kpe[(size_t)t * D_ROPE + 2 * p + 1] = x1 * s + x2 * c;
        }
    }
}

// ---------------- causal flash attention ----------------
// grid (32, 16): (q-tile of 64, head). 256 threads.
// Thread (a = tid/8, g = tid%8) owns q rows {2a, 2a+1}, keys kj = j*8+g (j<4),
// and V dims {i4*32 + 4g .. +3} (4 float4 chunks per q row).
#define SQ_LD 196   // 192 padded; (196*2a)%32 = 8a -> conflict-free q loads
#define SK_LD 196   // rows g apart -> banks 4g -> conflict-free k loads
#define SS_LD 33
#define ATTN_SMEM_FLOATS (64 * SQ_LD + 32 * SK_LD + 32 * 128 + 64 * SS_LD)

__global__ __launch_bounds__(256, 2) void attn_kernel(
    const float* __restrict__ q, const float* __restrict__ kv,
    const float* __restrict__ kpe, float* __restrict__ out)
{
    extern __shared__ float sm[];
    float* sQ = sm;                   // 64 x SQ_LD
    float* sK = sQ + 64 * SQ_LD;      // 32 x SK_LD
    float* sV = sK + 32 * SK_LD;      // 32 x 128
    float* sS = sV + 32 * 128;        // 64 x SS_LD

    const int h   = blockIdx.y;
    const int t0  = blockIdx.x * 64;
    const int tid = threadIdx.x;
    const int a   = tid >> 3;
    const int g   = tid & 7;

    // load Q tile (once)
    for (int i = tid; i < 64 * 192; i += 256) {
        const int r = i / 192, d = i - r * 192;
        sQ[r * SQ_LD + d] = q[(size_t)(t0 + r) * (NH * D_QK) + h * D_QK + d];
    }

    float acc0[16], acc1[16];
#pragma unroll
    for (int i = 0; i < 16; i++) { acc0[i] = 0.f; acc1[i] = 0.f; }
    float m0 = -1e30f, m1 = -1e30f, l0 = 0.f, l1 = 0.f;

    const int r0g = t0 + 2 * a, r1g = r0g + 1;

    for (int k0 = 0; k0 < t0 + 64; k0 += 32) {
        __syncthreads();
        // load K tile (k_nope ++ k_pe) and V tile
        for (int i = tid; i < 32 * 192; i += 256) {
            const int r = i / 192, d = i - r * 192;
            const float v = (d < 128)
                ? kv[(size_t)(k0 + r) * (NH * 256) + h * 256 + d]
                : kpe[(size_t)(k0 + r) * D_ROPE + (d - 128)];
            sK[r * SK_LD + d] = v;
        }
        for (int i = tid; i < 32 * 128; i += 256) {
            const int r = i >> 7, d = i & 127;
            sV[i] = kv[(size_t)(k0 + r) * (NH * 256) + h * 256 + 128 + d];
        }
        __syncthreads();

        // ---- scores: 2 q rows x 4 keys ----
        float s0[4] = {0.f, 0.f, 0.f, 0.f};
        float s1[4] = {0.f, 0.f, 0.f, 0.f};
        const float4* q0 = (const float4*)(sQ + (2 * a) * SQ_LD);
        const float4* q1 = (const float4*)(sQ + (2 * a + 1) * SQ_LD);
#pragma unroll 4
        for (int d4 = 0; d4 < 48; d4++) {
            const float4 qa = q0[d4];
            const float4 qb = q1[d4];
#pragma unroll
            for (int j = 0; j < 4; j++) {
                const float4 kk = *(const float4*)(sK + (j * 8 + g) * SK_LD + 4 * d4);
                s0[j] += qa.x * kk.x + qa.y * kk.y + qa.z * kk.z + qa.w * kk.w;
                s1[j] += qb.x * kk.x + qb.y * kk.y + qb.z * kk.z + qb.w * kk.w;
            }
        }
#pragma unroll
        for (int j = 0; j < 4; j++) {
            const int kg = k0 + j * 8 + g;
            s0[j] = (r0g >= kg) ? s0[j] * SCALING : -1e30f;
            s1[j] = (r1g >= kg) ? s1[j] * SCALING : -1e30f;
        }

        // ---- online softmax over 8-lane groups ----
        float mt0 = fmaxf(fmaxf(s0[0], s0[1]), fmaxf(s0[2], s0[3]));
        float mt1 = fmaxf(fmaxf(s1[0], s1[1]), fmaxf(s1[2], s1[3]));
#pragma unroll
        for (int o = 4; o; o >>= 1) {
            mt0 = fmaxf(mt0, __shfl_xor_sync(0xffffffffu, mt0, o));
            mt1 = fmaxf(mt1, __shfl_xor_sync(0xffffffffu, mt1, o));
        }
        const float mn0 = fmaxf(m0, mt0), mn1 = fmaxf(m1, mt1);
        const float sc0 = __expf(m0 - mn0), sc1 = __expf(m1 - mn1);
        float ps0 = 0.f, ps1 = 0.f;
#pragma unroll
        for (int j = 0; j < 4; j++) {
            s0[j] = __expf(s0[j] - mn0); ps0 += s0[j];
            s1[j] = __expf(s1[j] - mn1); ps1 += s1[j];
        }
#pragma unroll
        for (int o = 4; o; o >>= 1) {
            ps0 += __shfl_xor_sync(0xffffffffu, ps0, o);
            ps1 += __shfl_xor_sync(0xffffffffu, ps1, o);
        }
        l0 = l0 * sc0 + ps0; m0 = mn0;
        l1 = l1 * sc1 + ps1; m1 = mn1;
#pragma unroll
        for (int i = 0; i < 16; i++) { acc0[i] *= sc0; acc1[i] *= sc1; }
#pragma unroll
        for (int j = 0; j < 4; j++) {
            sS[(2 * a) * SS_LD + j * 8 + g]     = s0[j];
            sS[(2 * a + 1) * SS_LD + j * 8 + g] = s1[j];
        }
        __syncthreads();

        // ---- P @ V ----
#pragma unroll 4
        for (int j = 0; j < 32; j++) {
            const float p0 = sS[(2 * a) * SS_LD + j];
            const float p1 = sS[(2 * a + 1) * SS_LD + j];
            const float4* vr = (const float4*)(sV + j * 128);
#pragma unroll
            for (int i4 = 0; i4 < 4; i4++) {
                const float4 vv = vr[i4 * 8 + g];
                acc0[i4 * 4 + 0] += p0 * vv.x;
                acc0[i4 * 4 + 1] += p0 * vv.y;
                acc0[i4 * 4 + 2] += p0 * vv.z;
                acc0[i4 * 4 + 3] += p0 * vv.w;
                acc1[i4 * 4 + 0] += p1 * vv.x;
                acc1[i4 * 4 + 1] += p1 * vv.y;
                acc1[i4 * 4 + 2] += p1 * vv.z;
                acc1[i4 * 4 + 3] += p1 * vv.w;
            }
        }
    }

    const float il0 = 1.f / l0, il1 = 1.f / l1;
#pragma unroll
    for (int i4 = 0; i4 < 4; i4++) {
        float4 o0 = make_float4(acc0[i4 * 4 + 0] * il0, acc0[i4 * 4 + 1] * il0,
                                acc0[i4 * 4 + 2] * il0, acc0[i4 * 4 + 3] * il0);
        float4 o1 = make_float4(acc1[i4 * 4 + 0] * il1, acc1[i4 * 4 + 1] * il1,
                                acc1[i4 * 4 + 2] * il1, acc1[i4 * 4 + 3] * il1);
        *(float4*)(out + (size_t)r0g * (NH * D_V) + h * D_V + i4 * 32 + g * 4) = o0;
        *(float4*)(out + (size_t)r1g * (NH * D_V) + h * D_V + i4 * 32 + g * 4) = o1;
    }
}

// ---------------- launch ----------------
extern "C" void kernel_launch(void* const* d_in, const int* in_sizes, int n_in,
                              void* d_out, int out_size)
{
    const float* hidden    = (const float*)d_in[0];
    const int*   positions = (const int*)  d_in[1];
    const float* w_qkv_a   = (const float*)d_in[2];
    const float* gamma_q   = (const float*)d_in[3];
    const float* w_q_b     = (const float*)d_in[4];
    const float* gamma_kv  = (const float*)d_in[5];
    const float* w_kv_b    = (const float*)d_in[6];
    const float* w_o       = (const float*)d_in[7];
    float* out = (float*)d_out;

    float *qkv_a, *qn, *kvn, *qbuf, *kvbuf, *kpe, *attn;
    cudaGetSymbolAddress((void**)&qkv_a, g_qkv_a);
    cudaGetSymbolAddress((void**)&qn,    g_qn);
    cudaGetSymbolAddress((void**)&kvn,   g_kvn);
    cudaGetSymbolAddress((void**)&qbuf,  g_qbuf);
    cudaGetSymbolAddress((void**)&kvbuf, g_kvbuf);
    cudaGetSymbolAddress((void**)&kpe,   g_kpe);
    cudaGetSymbolAddress((void**)&attn,  g_attn);

    // 1) qkv_a = hidden @ w_qkv_a        [2048 x 2112]
    sgemm_kernel<<<dim3(QKV_A_N / 64, T_TOK / 128), 256>>>(
        hidden, w_qkv_a, qkv_a, T_TOK, QKV_A_N, HID);

    // 2) RMSNorm of q / kv latents
    rmsnorm_kernel<<<T_TOK, 256>>>(qkv_a, QKV_A_N, 0,      Q_LORA,  gamma_q,  qn);
    rmsnorm_kernel<<<T_TOK, 256>>>(qkv_a, QKV_A_N, Q_LORA, KV_LORA, gamma_kv, kvn);

    // 3) q = qn @ w_q_b                  [2048 x 3072]
    sgemm_kernel<<<dim3((NH * D_QK) / 64, T_TOK / 128), 256>>>(
        qn, w_q_b, qbuf, T_TOK, NH * D_QK, Q_LORA);

    // 4) kv = kvn @ w_kv_b               [2048 x 4096]
    sgemm_kernel<<<dim3((NH * 256) / 64, T_TOK / 128), 256>>>(
        kvn, w_kv_b, kvbuf, T_TOK, NH * 256, KV_LORA);

    // 5) RoPE on q_pe (in place) and k_pe (to g_kpe)
    rope_kernel<<<T_TOK, 256>>>(qbuf, qkv_a, kpe, positions);

    // 6) causal flash attention -> attn  [2048 x 2048]
    static const int attn_smem = ATTN_SMEM_FLOATS * (int)sizeof(float);
    cudaFuncSetAttribute(attn_kernel, cudaFuncAttributeMaxDynamicSharedMemorySize, attn_smem);
    attn_kernel<<<dim3(T_TOK / 64, NH), 256, attn_smem>>>(qbuf, kvbuf, kpe, attn);

    // 7) out = attn @ w_o                [2048 x 2048]
    sgemm_kernel<<<dim3(HID / 64, T_TOK / 128), 256>>>(
        attn, w_o, out, T_TOK, HID, NH * D_V);
}

// round 3
// speedup vs baseline: 1.2202x; 1.2202x over previous
#include <cuda_runtime.h>
#include <cuda_bf16.h>
#include <mma.h>
#include <math.h>
#include <stdint.h>

using namespace nvcuda;

// ---------------- problem constants ----------------
#define T_TOK   2048
#define HID     2048
#define NH      16
#define D_NOPE  128
#define D_ROPE  64
#define D_QK    192           // 128 + 64
#define D_V     128
#define Q_LORA  1536
#define KV_LORA 512
#define QKV_A_N 2112          // Q_LORA + KV_LORA + D_ROPE
#define SCALING 0.07216878364870322f   // 192^-0.5

// ---------------- scratch (device globals, no allocation) ----------------
__device__ __align__(128) float g_qkv_a [T_TOK * QKV_A_N];       // 2048 x 2112
__device__ __align__(128) float g_qn    [T_TOK * Q_LORA];        // 2048 x 1536
__device__ __align__(128) float g_kvn   [T_TOK * KV_LORA];       // 2048 x 512
__device__ __align__(128) float g_qbuf  [T_TOK * NH * D_QK];     // 2048 x 3072
__device__ __align__(128) float g_kvbuf [T_TOK * NH * 256];      // 2048 x 4096
__device__ __align__(128) float g_kpe   [T_TOK * D_ROPE];        // 2048 x 64
__device__ __align__(128) float g_attn  [T_TOK * NH * D_V];      // 2048 x 2048

// ---------------- cp.async helpers ----------------
__device__ __forceinline__ void cp16(void* s, const void* g) {
    unsigned int sa = (unsigned int)__cvta_generic_to_shared(s);
    asm volatile("cp.async.cg.shared.global [%0], [%1], 16;" :: "r"(sa), "l"(g));
}
#define CP_COMMIT() asm volatile("cp.async.commit_group;")
#define CP_WAIT1()  asm volatile("cp.async.wait_group 1;")
#define CP_WAIT0()  asm volatile("cp.async.wait_group 0;")

// ---------------- tf32 tensor-core GEMM: C[M,N] = A[M,K] @ B[K,N] ----------------
// BM=128, BN=64, BK=16, 256 threads, warp grid 4(m) x 2(n), warp tile 32x32.
// Requires M%128==0, N%64==0, K%16==0 (true for all 4 GEMMs here).
#define GBM 128
#define GBN 64
#define GBK 16

typedef wmma::fragment<wmma::matrix_a, 16, 16, 8, wmma::precision::tf32, wmma::row_major> FragA;
typedef wmma::fragment<wmma::matrix_b, 16, 16, 8, wmma::precision::tf32, wmma::row_major> FragB;
typedef wmma::fragment<wmma::accumulator, 16, 16, 8, float> FragC;

__global__ __launch_bounds__(256) void tc_gemm(
    const float* __restrict__ A, const float* __restrict__ B,
    float* __restrict__ C, int M, int N, int K)
{
    __shared__ float sA[2][GBM * GBK];   // 8 KB per stage
    __shared__ float sB[2][GBK * GBN];   // 4 KB per stage

    const int tid  = threadIdx.x;
    const int warp = tid >> 5;
    const int wm   = warp >> 1;          // 0..3 -> row offset wm*32
    const int wn   = warp & 1;           // 0..1 -> col offset wn*32
    const int row0 = blockIdx.y * GBM;
    const int col0 = blockIdx.x * GBN;

    FragC acc[2][2];
#pragma unroll
    for (int i = 0; i < 2; i++)
#pragma unroll
        for (int j = 0; j < 2; j++) wmma::fill_fragment(acc[i][j], 0.f);

    // load indices
    const int ar  = tid >> 2;            // 0..63  (two rounds: ar, ar+64)
    const int ac4 = (tid & 3) << 2;      // 0,4,8,12
    const int br  = tid >> 4;            // 0..15
    const int bc4 = (tid & 15) << 2;     // 0..60

    const float* Abase = A + (size_t)(row0 + ar) * K + ac4;
    const float* Bbase = B + (size_t)br * N + col0 + bc4;

    // prologue: issue stage 0
    cp16(&sA[0][ar * GBK + ac4],        Abase);
    cp16(&sA[0][(ar + 64) * GBK + ac4], Abase + (size_t)64 * K);
    cp16(&sB[0][br * GBN + bc4],        Bbase);
    CP_COMMIT();

    int buf = 0;
    for (int k0 = 0; k0 < K; k0 += GBK) {
        const bool has_next = (k0 + GBK) < K;
        if (has_next) {
            const int nb = buf ^ 1;
            cp16(&sA[nb][ar * GBK + ac4],        Abase + k0 + GBK);
            cp16(&sA[nb][(ar + 64) * GBK + ac4], Abase + (size_t)64 * K + k0 + GBK);
            cp16(&sB[nb][br * GBN + bc4],        Bbase + (size_t)(k0 + GBK) * N);
            CP_COMMIT();
            CP_WAIT1();
        } else {
            CP_WAIT0();
        }
        __syncthreads();

#pragma unroll
        for (int kk = 0; kk < GBK; kk += 8) {
            FragA af[2];
            FragB bf[2];
#pragma unroll
            for (int i = 0; i < 2; i++) {
                wmma::load_matrix_sync(af[i], &sA[buf][(wm * 32 + i * 16) * GBK + kk], GBK);
#pragma unroll
                for (int e = 0; e < af[i].num_elements; e++)
                    af[i].x[e] = wmma::__float_to_tf32(af[i].x[e]);
            }
#pragma unroll
            for (int j = 0; j < 2; j++) {
                wmma::load_matrix_sync(bf[j], &sB[buf][kk * GBN + wn * 32 + j * 16], GBN);
#pragma unroll
                for (int e = 0; e < bf[j].num_elements; e++)
                    bf[j].x[e] = wmma::__float_to_tf32(bf[j].x[e]);
            }
#pragma unroll
            for (int i = 0; i < 2; i++)
#pragma unroll
                for (int j = 0; j < 2; j++)
                    wmma::mma_sync(acc[i][j], af[i], bf[j], acc[i][j]);
        }
        __syncthreads();
        buf ^= 1;
    }

#pragma unroll
    for (int i = 0; i < 2; i++)
#pragma unroll
        for (int j = 0; j < 2; j++)
            wmma::store_matrix_sync(
                C + (size_t)(row0 + wm * 32 + i * 16) * N + col0 + wn * 32 + j * 16,
                acc[i][j], N, wmma::mem_row_major);
}

// ---------------- RMSNorm ----------------
__global__ __launch_bounds__(256) void rmsnorm_kernel(
    const float* __restrict__ in, int ld, int off, int width,
    const float* __restrict__ gamma, float* __restrict__ out)
{
    const int row = blockIdx.x;
    const float* x = in + (size_t)row * ld + off;
    float ss = 0.f;
    for (int i = threadIdx.x; i < width; i += 256) {
        float v = x[i];
        ss += v * v;
    }
#pragma unroll
    for (int o = 16; o; o >>= 1) ss += __shfl_xor_sync(0xffffffffu, ss, o);
    __shared__ float warp_s[8];
    __shared__ float s_inv;
    if ((threadIdx.x & 31) == 0) warp_s[threadIdx.x >> 5] = ss;
    __syncthreads();
    if (threadIdx.x == 0) {
        float t = 0.f;
#pragma unroll
        for (int i = 0; i < 8; i++) t += warp_s[i];
        s_inv = rsqrtf(t / (float)width + 1e-6f);
    }
    __syncthreads();
    const float inv = s_inv;
    float* o = out + (size_t)row * width;
    for (int i = threadIdx.x; i < width; i += 256)
        o[i] = x[i] * inv * gamma[i];
}

// ---------------- RoPE ----------------
__global__ __launch_bounds__(256) void rope_kernel(
    float* __restrict__ q, const float* __restrict__ qkv_a,
    float* __restrict__ kpe, const int* __restrict__ positions)
{
    const int t = blockIdx.x;
    const float pos = (float)positions[t];
    for (int i = threadIdx.x; i < NH * 32 + 32; i += 256) {
        if (i < NH * 32) {
            const int h = i >> 5, p = i & 31;
            const float inv = powf(10000.0f, -(float)p / 32.0f);
            float s, c;
            sincosf(pos * inv, &s, &c);
            float* base = q + (size_t)t * (NH * D_QK) + h * D_QK + D_NOPE;
            const float x1 = base[2 * p], x2 = base[2 * p + 1];
            base[2 * p]     = x1 * c - x2 * s;
            base[2 * p + 1] = x1 * s + x2 * c;
        } else {
            const int p = i - NH * 32;
            const float inv = powf(10000.0f, -(float)p / 32.0f);
            float s, c;
            sincosf(pos * inv, &s, &c);
            const float* src = qkv_a + (size_t)t * QKV_A_N + (Q_LORA + KV_LORA);
            const float x1 = src[2 * p], x2 = src[2 * p + 1];
            kpe[(size_t)t * D_ROPE + 2 * p]     = x1 * c - x2 * s;
            kpe[(size_t)t * D_ROPE + 2 * p + 1] = x1 * s + x2 * c;
        }
    }
}

// ---------------- causal flash attention (fp32) ----------------
#define SQ_LD 196
#define SK_LD 196
#define SS_LD 33
#define ATTN_SMEM_FLOATS (64 * SQ_LD + 32 * SK_LD + 32 * 128 + 64 * SS_LD)

__global__ __launch_bounds__(256, 2) void attn_kernel(
    const float* __restrict__ q, const float* __restrict__ kv,
    const float* __restrict__ kpe, float* __restrict__ out)
{
    extern __shared__ float sm[];
    float* sQ = sm;                   // 64 x SQ_LD
    float* sK = sQ + 64 * SQ_LD;      // 32 x SK_LD
    float* sV = sK + 32 * SK_LD;      // 32 x 128
    float* sS = sV + 32 * 128;        // 64 x SS_LD

    const int h   = blockIdx.y;
    const int t0  = blockIdx.x * 64;
    const int tid = threadIdx.x;
    const int a   = tid >> 3;
    const int g   = tid & 7;

    for (int i = tid; i < 64 * 192; i += 256) {
        const int r = i / 192, d = i - r * 192;
        sQ[r * SQ_LD + d] = q[(size_t)(t0 + r) * (NH * D_QK) + h * D_QK + d];
    }

    float acc0[16], acc1[16];
#pragma unroll
    for (int i = 0; i < 16; i++) { acc0[i] = 0.f; acc1[i] = 0.f; }
    float m0 = -1e30f, m1 = -1e30f, l0 = 0.f, l1 = 0.f;

    const int r0g = t0 + 2 * a, r1g = r0g + 1;

    for (int k0 = 0; k0 < t0 + 64; k0 += 32) {
        __syncthreads();
        for (int i = tid; i < 32 * 192; i += 256) {
            const int r = i / 192, d = i - r * 192;
            const float v = (d < 128)
                ? kv[(size_t)(k0 + r) * (NH * 256) + h * 256 + d]
                : kpe[(size_t)(k0 + r) * D_ROPE + (d - 128)];
            sK[r * SK_LD + d] = v;
        }
        for (int i = tid; i < 32 * 128; i += 256) {
            const int r = i >> 7, d = i & 127;
            sV[i] = kv[(size_t)(k0 + r) * (NH * 256) + h * 256 + 128 + d];
        }
        __syncthreads();

        float s0[4] = {0.f, 0.f, 0.f, 0.f};
        float s1[4] = {0.f, 0.f, 0.f, 0.f};
        const float4* q0 = (const float4*)(sQ + (2 * a) * SQ_LD);
        const float4* q1 = (const float4*)(sQ + (2 * a + 1) * SQ_LD);
#pragma unroll 4
        for (int d4 = 0; d4 < 48; d4++) {
            const float4 qa = q0[d4];
            const float4 qb = q1[d4];
#pragma unroll
            for (int j = 0; j < 4; j++) {
                const float4 kk = *(const float4*)(sK + (j * 8 + g) * SK_LD + 4 * d4);
                s0[j] += qa.x * kk.x + qa.y * kk.y + qa.z * kk.z + qa.w * kk.w;
                s1[j] += qb.x * kk.x + qb.y * kk.y + qb.z * kk.z + qb.w * kk.w;
            }
        }
#pragma unroll
        for (int j = 0; j < 4; j++) {
            const int kg = k0 + j * 8 + g;
            s0[j] = (r0g >= kg) ? s0[j] * SCALING : -1e30f;
            s1[j] = (r1g >= kg) ? s1[j] * SCALING : -1e30f;
        }

        float mt0 = fmaxf(fmaxf(s0[0], s0[1]), fmaxf(s0[2], s0[3]));
        float mt1 = fmaxf(fmaxf(s1[0], s1[1]), fmaxf(s1[2], s1[3]));
#pragma unroll
        for (int o = 4; o; o >>= 1) {
            mt0 = fmaxf(mt0, __shfl_xor_sync(0xffffffffu, mt0, o));
            mt1 = fmaxf(mt1, __shfl_xor_sync(0xffffffffu, mt1, o));
        }
        const float mn0 = fmaxf(m0, mt0), mn1 = fmaxf(m1, mt1);
        const float sc0 = __expf(m0 - mn0), sc1 = __expf(m1 - mn1);
        float ps0 = 0.f, ps1 = 0.f;
#pragma unroll
        for (int j = 0; j < 4; j++) {
            s0[j] = __expf(s0[j] - mn0); ps0 += s0[j];
            s1[j] = __expf(s1[j] - mn1); ps1 += s1[j];
        }
#pragma unroll
        for (int o = 4; o; o >>= 1) {
            ps0 += __shfl_xor_sync(0xffffffffu, ps0, o);
            ps1 += __shfl_xor_sync(0xffffffffu, ps1, o);
        }
        l0 = l0 * sc0 + ps0; m0 = mn0;
        l1 = l1 * sc1 + ps1; m1 = mn1;
#pragma unroll
        for (int i = 0; i < 16; i++) { acc0[i] *= sc0; acc1[i] *= sc1; }
#pragma unroll
        for (int j = 0; j < 4; j++) {
            sS[(2 * a) * SS_LD + j * 8 + g]     = s0[j];
            sS[(2 * a + 1) * SS_LD + j * 8 + g] = s1[j];
        }
        __syncthreads();

#pragma unroll 4
        for (int j = 0; j < 32; j++) {
            const float p0 = sS[(2 * a) * SS_LD + j];
            const float p1 = sS[(2 * a + 1) * SS_LD + j];
            const float4* vr = (const float4*)(sV + j * 128);
#pragma unroll
            for (int i4 = 0; i4 < 4; i4++) {
                const float4 vv = vr[i4 * 8 + g];
                acc0[i4 * 4 + 0] += p0 * vv.x;
                acc0[i4 * 4 + 1] += p0 * vv.y;
                acc0[i4 * 4 + 2] += p0 * vv.z;
                acc0[i4 * 4 + 3] += p0 * vv.w;
                acc1[i4 * 4 + 0] += p1 * vv.x;
                acc1[i4 * 4 + 1] += p1 * vv.y;
                acc1[i4 * 4 + 2] += p1 * vv.z;
                acc1[i4 * 4 + 3] += p1 * vv.w;
            }
        }
    }

    const float il0 = 1.f / l0, il1 = 1.f / l1;
#pragma unroll
    for (int i4 = 0; i4 < 4; i4++) {
        float4 o0 = make_float4(acc0[i4 * 4 + 0] * il0, acc0[i4 * 4 + 1] * il0,
                                acc0[i4 * 4 + 2] * il0, acc0[i4 * 4 + 3] * il0);
        float4 o1 = make_float4(acc1[i4 * 4 + 0] * il1, acc1[i4 * 4 + 1] * il1,
                                acc1[i4 * 4 + 2] * il1, acc1[i4 * 4 + 3] * il1);
        *(float4*)(out + (size_t)r0g * (NH * D_V) + h * D_V + i4 * 32 + g * 4) = o0;
        *(float4*)(out + (size_t)r1g * (NH * D_V) + h * D_V + i4 * 32 + g * 4) = o1;
    }
}

// ---------------- launch ----------------
extern "C" void kernel_launch(void* const* d_in, const int* in_sizes, int n_in,
                              void* d_out, int out_size)
{
    const float* hidden    = (const float*)d_in[0];
    const int*   positions = (const int*)  d_in[1];
    const float* w_qkv_a   = (const float*)d_in[2];
    const float* gamma_q   = (const float*)d_in[3];
    const float* w_q_b     = (const float*)d_in[4];
    const float* gamma_kv  = (const float*)d_in[5];
    const float* w_kv_b    = (const float*)d_in[6];
    const float* w_o       = (const float*)d_in[7];
    float* out = (float*)d_out;

    float *qkv_a, *qn, *kvn, *qbuf, *kvbuf, *kpe, *attn;
    cudaGetSymbolAddress((void**)&qkv_a, g_qkv_a);
    cudaGetSymbolAddress((void**)&qn,    g_qn);
    cudaGetSymbolAddress((void**)&kvn,   g_kvn);
    cudaGetSymbolAddress((void**)&qbuf,  g_qbuf);
    cudaGetSymbolAddress((void**)&kvbuf, g_kvbuf);
    cudaGetSymbolAddress((void**)&kpe,   g_kpe);
    cudaGetSymbolAddress((void**)&attn,  g_attn);

    // 1) qkv_a = hidden @ w_qkv_a        [2048 x 2112]
    tc_gemm<<<dim3(QKV_A_N / GBN, T_TOK / GBM), 256>>>(
        hidden, w_qkv_a, qkv_a, T_TOK, QKV_A_N, HID);

    // 2) RMSNorm of q / kv latents
    rmsnorm_kernel<<<T_TOK, 256>>>(qkv_a, QKV_A_N, 0,      Q_LORA,  gamma_q,  qn);
    rmsnorm_kernel<<<T_TOK, 256>>>(qkv_a, QKV_A_N, Q_LORA, KV_LORA, gamma_kv, kvn);

    // 3) q = qn @ w_q_b                  [2048 x 3072]
    tc_gemm<<<dim3((NH * D_QK) / GBN, T_TOK / GBM), 256>>>(
        qn, w_q_b, qbuf, T_TOK, NH * D_QK, Q_LORA);

    // 4) kv = kvn @ w_kv_b               [2048 x 4096]
    tc_gemm<<<dim3((NH * 256) / GBN, T_TOK / GBM), 256>>>(
        kvn, w_kv_b, kvbuf, T_TOK, NH * 256, KV_LORA);

    // 5) RoPE on q_pe (in place) and k_pe
    rope_kernel<<<T_TOK, 256>>>(qbuf, qkv_a, kpe, positions);

    // 6) causal flash attention -> attn  [2048 x 2048]
    static const int attn_smem = ATTN_SMEM_FLOATS * (int)sizeof(float);
    cudaFuncSetAttribute(attn_kernel, cudaFuncAttributeMaxDynamicSharedMemorySize, attn_smem);
    attn_kernel<<<dim3(T_TOK / 64, NH), 256, attn_smem>>>(qbuf, kvbuf, kpe, attn);

    // 7) out = attn @ w_o                [2048 x 2048]
    tc_gemm<<<dim3(HID / GBN, T_TOK / GBM), 256>>>(
        attn, w_o, out, T_TOK, HID, NH * D_V);
}

// round 4
// speedup vs baseline: 1.6806x; 1.3773x over previous
#include <cuda_runtime.h>
#include <cuda_bf16.h>
#include <mma.h>
#include <math.h>
#include <stdint.h>

using namespace nvcuda;

// ---------------- problem constants ----------------
#define T_TOK   2048
#define HID     2048
#define NH      16
#define D_NOPE  128
#define D_ROPE  64
#define D_QK    192
#define D_V     128
#define Q_LORA  1536
#define KV_LORA 512
#define QKV_A_N 2112
#define SCALING 0.07216878364870322f   // 192^-0.5

// ---------------- scratch ----------------
__device__ __align__(128) float g_qkv_a [T_TOK * QKV_A_N];
__device__ __align__(128) float g_qn    [T_TOK * Q_LORA];
__device__ __align__(128) float g_kvn   [T_TOK * KV_LORA];
__device__ __align__(128) float g_qbuf  [T_TOK * NH * D_QK];
__device__ __align__(128) float g_kvbuf [T_TOK * NH * 256];
__device__ __align__(128) float g_kpe   [T_TOK * D_ROPE];
__device__ __align__(128) float g_attn  [T_TOK * NH * D_V];

// ---------------- helpers ----------------
__device__ __forceinline__ void cp16(void* s, const void* g) {
    unsigned int sa = (unsigned int)__cvta_generic_to_shared(s);
    asm volatile("cp.async.cg.shared.global [%0], [%1], 16;" :: "r"(sa), "l"(g));
}
#define CP_COMMIT() asm volatile("cp.async.commit_group;")
#define CP_WAIT1()  asm volatile("cp.async.wait_group 1;")
#define CP_WAIT0()  asm volatile("cp.async.wait_group 0;")

__device__ __forceinline__ unsigned int f2tf(float x) {
    unsigned int u;
    asm("cvt.rna.tf32.f32 %0, %1;" : "=r"(u) : "f"(x));
    return u;
}
__device__ __forceinline__ void mma_tf32(float* c,
    unsigned int a0, unsigned int a1, unsigned int a2, unsigned int a3,
    unsigned int b0, unsigned int b1)
{
    asm volatile(
        "mma.sync.aligned.m16n8k8.row.col.f32.tf32.tf32.f32 "
        "{%0,%1,%2,%3},{%4,%5,%6,%7},{%8,%9},{%0,%1,%2,%3};"
        : "+f"(c[0]), "+f"(c[1]), "+f"(c[2]), "+f"(c[3])
        : "r"(a0), "r"(a1), "r"(a2), "r"(a3), "r"(b0), "r"(b1));
}

// ---------------- tf32 wmma GEMM: C[M,N] = A[M,K] @ B[K,N] ----------------
// BM=256, BN=64, BK=16; 8 warps (4m x 2n), warp tile 64x32.
#define GBM 256
#define GBN 64
#define GBK 16
#define LDA_S 20   // padded (conflict-free, mult of 4)
#define LDB_S 68
#define GEMM_SMEM_BYTES ((2 * GBM * LDA_S + 2 * GBK * LDB_S) * 4)

typedef wmma::fragment<wmma::matrix_a, 16, 16, 8, wmma::precision::tf32, wmma::row_major> FragA;
typedef wmma::fragment<wmma::matrix_b, 16, 16, 8, wmma::precision::tf32, wmma::row_major> FragB;
typedef wmma::fragment<wmma::accumulator, 16, 16, 8, float> FragC;

__global__ __launch_bounds__(256) void tc_gemm(
    const float* __restrict__ A, const float* __restrict__ B,
    float* __restrict__ C, int M, int N, int K)
{
    extern __shared__ float smg[];
    float* sA = smg;                       // 2 stages of 256*20
    float* sB = smg + 2 * GBM * LDA_S;     // 2 stages of 16*68

    const int tid  = threadIdx.x;
    const int warp = tid >> 5;
    const int wm   = warp >> 1;            // 0..3 -> row wm*64
    const int wn   = warp & 1;             // 0..1 -> col wn*32
    const int row0 = blockIdx.y * GBM;
    const int col0 = blockIdx.x * GBN;

    FragC acc[4][2];
#pragma unroll
    for (int i = 0; i < 4; i++)
#pragma unroll
        for (int j = 0; j < 2; j++) wmma::fill_fragment(acc[i][j], 0.f);

    const int ar  = tid >> 2;              // 0..63 (rows ar + 64j)
    const int ac4 = (tid & 3) << 2;
    const int br  = tid >> 4;              // 0..15
    const int bc4 = (tid & 15) << 2;

    const float* Abase = A + (size_t)(row0 + ar) * K + ac4;
    const float* Bbase = B + (size_t)br * N + col0 + bc4;

#pragma unroll
    for (int j = 0; j < 4; j++)
        cp16(&sA[(ar + 64 * j) * LDA_S + ac4], Abase + (size_t)(64 * j) * K);
    cp16(&sB[br * LDB_S + bc4], Bbase);
    CP_COMMIT();

    int buf = 0;
    for (int k0 = 0; k0 < K; k0 += GBK) {
        if (k0 + GBK < K) {
            const int nb = buf ^ 1;
#pragma unroll
            for (int j = 0; j < 4; j++)
                cp16(&sA[nb * GBM * LDA_S + (ar + 64 * j) * LDA_S + ac4],
                     Abase + (size_t)(64 * j) * K + k0 + GBK);
            cp16(&sB[nb * GBK * LDB_S + br * LDB_S + bc4],
                 Bbase + (size_t)(k0 + GBK) * N);
            CP_COMMIT();
            CP_WAIT1();
        } else {
            CP_WAIT0();
        }
        __syncthreads();

        const float* cA = sA + buf * GBM * LDA_S;
        const float* cB = sB + buf * GBK * LDB_S;
#pragma unroll
        for (int kk = 0; kk < GBK; kk += 8) {
            FragA af[4];
            FragB bf[2];
#pragma unroll
            for (int i = 0; i < 4; i++) {
                wmma::load_matrix_sync(af[i], cA + (wm * 64 + i * 16) * LDA_S + kk, LDA_S);
#pragma unroll
                for (int e = 0; e < af[i].num_elements; e++)
                    af[i].x[e] = wmma::__float_to_tf32(af[i].x[e]);
            }
#pragma unroll
            for (int j = 0; j < 2; j++) {
                wmma::load_matrix_sync(bf[j], cB + kk * LDB_S + wn * 32 + j * 16, LDB_S);
#pragma unroll
                for (int e = 0; e < bf[j].num_elements; e++)
                    bf[j].x[e] = wmma::__float_to_tf32(bf[j].x[e]);
            }
#pragma unroll
            for (int i = 0; i < 4; i++)
#pragma unroll
                for (int j = 0; j < 2; j++)
                    wmma::mma_sync(acc[i][j], af[i], bf[j], acc[i][j]);
        }
        __syncthreads();
        buf ^= 1;
    }

#pragma unroll
    for (int i = 0; i < 4; i++)
#pragma unroll
        for (int j = 0; j < 2; j++)
            wmma::store_matrix_sync(
                C + (size_t)(row0 + wm * 64 + i * 16) * N + col0 + wn * 32 + j * 16,
                acc[i][j], N, wmma::mem_row_major);
}

// ---------------- RMSNorm ----------------
__global__ __launch_bounds__(256) void rmsnorm_kernel(
    const float* __restrict__ in, int ld, int off, int width,
    const float* __restrict__ gamma, float* __restrict__ out)
{
    const int row = blockIdx.x;
    const float* x = in + (size_t)row * ld + off;
    float ss = 0.f;
    for (int i = threadIdx.x; i < width; i += 256) {
        float v = x[i];
        ss += v * v;
    }
#pragma unroll
    for (int o = 16; o; o >>= 1) ss += __shfl_xor_sync(0xffffffffu, ss, o);
    __shared__ float warp_s[8];
    __shared__ float s_inv;
    if ((threadIdx.x & 31) == 0) warp_s[threadIdx.x >> 5] = ss;
    __syncthreads();
    if (threadIdx.x == 0) {
        float t = 0.f;
#pragma unroll
        for (int i = 0; i < 8; i++) t += warp_s[i];
        s_inv = rsqrtf(t / (float)width + 1e-6f);
    }
    __syncthreads();
    const float inv = s_inv;
    float* o = out + (size_t)row * width;
    for (int i = threadIdx.x; i < width; i += 256)
        o[i] = x[i] * inv * gamma[i];
}

// ---------------- RoPE ----------------
__global__ __launch_bounds__(256) void rope_kernel(
    float* __restrict__ q, const float* __restrict__ qkv_a,
    float* __restrict__ kpe, const int* __restrict__ positions)
{
    const int t = blockIdx.x;
    const float pos = (float)positions[t];
    for (int i = threadIdx.x; i < NH * 32 + 32; i += 256) {
        if (i < NH * 32) {
            const int h = i >> 5, p = i & 31;
            const float inv = powf(10000.0f, -(float)p / 32.0f);
            float s, c;
            sincosf(pos * inv, &s, &c);
            float* base = q + (size_t)t * (NH * D_QK) + h * D_QK + D_NOPE;
            const float x1 = base[2 * p], x2 = base[2 * p + 1];
            base[2 * p]     = x1 * c - x2 * s;
            base[2 * p + 1] = x1 * s + x2 * c;
        } else {
            const int p = i - NH * 32;
            const float inv = powf(10000.0f, -(float)p / 32.0f);
            float s, c;
            sincosf(pos * inv, &s, &c);
            const float* src = qkv_a + (size_t)t * QKV_A_N + (Q_LORA + KV_LORA);
            const float x1 = src[2 * p], x2 = src[2 * p + 1];
            kpe[(size_t)t * D_ROPE + 2 * p]     = x1 * c - x2 * s;
            kpe[(size_t)t * D_ROPE + 2 * p + 1] = x1 * s + x2 * c;
        }
    }
}

// ---------------- tensor-core causal flash attention ----------------
// Block = (q-tile 64, head). 8 warps. K-tile = 64.
// QK: warp (w&3 -> 16 rows, w>>2 -> 32 cols) of S[64x64].
// PV: warp (w&3 -> 16 rows, w>>2 -> 64 cols) of O[64x128].
#define AT_LDQ 196   // 192 pad -> banks 4g+t conflict-free
#define AT_LDV 136   // 128 pad -> banks 8t+g conflict-free
#define AT_LDP 68
#define AT_SMEM_FLOATS (64*AT_LDQ + 64*AT_LDQ + 64*AT_LDV + 64*AT_LDP + 128 + 128 + 64 + 64 + 64)

__global__ __launch_bounds__(256, 1) void attn_tc_kernel(
    const float* __restrict__ q, const float* __restrict__ kv,
    const float* __restrict__ kpe, float* __restrict__ out)
{
    extern __shared__ float sm[];
    float* sQ     = sm;                     // 64 x 196
    float* sK     = sQ + 64 * AT_LDQ;       // 64 x 196
    float* sV     = sK + 64 * AT_LDQ;       // 64 x 136
    float* sP     = sV + 64 * AT_LDV;       // 64 x 68
    float* sWmax  = sP + 64 * AT_LDP;       // [2][64]
    float* sWsum  = sWmax + 128;            // [2][64]
    float* sM     = sWsum + 128;            // 64
    float* sL     = sM + 64;                // 64
    float* sScale = sL + 64;                // 64

    const int h   = blockIdx.y;
    const int qt  = blockIdx.x;
    const int t0  = qt * 64;
    const int tid = threadIdx.x;
    const int w   = tid >> 5;
    const int lane = tid & 31;
    const int g   = lane >> 2;     // 0..7
    const int t   = lane & 3;      // 0..3
    const int mrow = (w & 3) * 16;
    const int nhalf = w >> 2;      // 0..1
    const int r0 = mrow + g, r1 = r0 + 8;

    // load Q tile
    for (int i = tid; i < 64 * 192; i += 256) {
        const int r = i / 192, d = i - r * 192;
        sQ[r * AT_LDQ + d] = q[(size_t)(t0 + r) * (NH * D_QK) + h * D_QK + d];
    }
    if (tid < 64) { sM[tid] = -1e30f; sL[tid] = 0.f; }

    float o[8][4];
#pragma unroll
    for (int i = 0; i < 8; i++)
#pragma unroll
        for (int j = 0; j < 4; j++) o[i][j] = 0.f;

    for (int kt = 0; kt <= qt; kt++) {
        const int k0 = kt * 64;
        __syncthreads();   // prev PV done; safe to overwrite sK/sV
        for (int i = tid; i < 64 * 192; i += 256) {
            const int r = i / 192, d = i - r * 192;
            sK[r * AT_LDQ + d] = (d < 128)
                ? kv[(size_t)(k0 + r) * (NH * 256) + h * 256 + d]
                : kpe[(size_t)(k0 + r) * D_ROPE + (d - 128)];
        }
        for (int i = tid; i < 64 * 128; i += 256) {
            const int r = i >> 7, d = i & 127;
            sV[r * AT_LDV + d] = kv[(size_t)(k0 + r) * (NH * 256) + h * 256 + 128 + d];
        }
        __syncthreads();

        // ---- S = Q @ K^T (warp patch 16x32) ----
        float s[4][4];
#pragma unroll
        for (int nt = 0; nt < 4; nt++)
#pragma unroll
            for (int j = 0; j < 4; j++) s[nt][j] = 0.f;

        const float* qb = sQ + r0 * AT_LDQ + t;
#pragma unroll 4
        for (int kk = 0; kk < 192; kk += 8) {
            const unsigned int a0 = f2tf(qb[kk]);
            const unsigned int a1 = f2tf(qb[8 * AT_LDQ + kk]);
            const unsigned int a2 = f2tf(qb[kk + 4]);
            const unsigned int a3 = f2tf(qb[8 * AT_LDQ + kk + 4]);
#pragma unroll
            for (int nt = 0; nt < 4; nt++) {
                const int key = nhalf * 32 + nt * 8 + g;
                const unsigned int b0 = f2tf(sK[key * AT_LDQ + kk + t]);
                const unsigned int b1 = f2tf(sK[key * AT_LDQ + kk + t + 4]);
                mma_tf32(s[nt], a0, a1, a2, a3, b0, b1);
            }
        }

        // scale + causal mask
        const int rg0 = t0 + r0, rg1 = t0 + r1;
#pragma unroll
        for (int nt = 0; nt < 4; nt++) {
            const int cg = k0 + nhalf * 32 + nt * 8 + 2 * t;
            s[nt][0] = (rg0 >= cg)     ? s[nt][0] * SCALING : -1e30f;
            s[nt][1] = (rg0 >= cg + 1) ? s[nt][1] * SCALING : -1e30f;
            s[nt][2] = (rg1 >= cg)     ? s[nt][2] * SCALING : -1e30f;
            s[nt][3] = (rg1 >= cg + 1) ? s[nt][3] * SCALING : -1e30f;
        }

        // row max (32-col half), quad reduce
        float mx0 = -1e30f, mx1 = -1e30f;
#pragma unroll
        for (int nt = 0; nt < 4; nt++) {
            mx0 = fmaxf(mx0, fmaxf(s[nt][0], s[nt][1]));
            mx1 = fmaxf(mx1, fmaxf(s[nt][2], s[nt][3]));
        }
        mx0 = fmaxf(mx0, __shfl_xor_sync(0xffffffffu, mx0, 1));
        mx0 = fmaxf(mx0, __shfl_xor_sync(0xffffffffu, mx0, 2));
        mx1 = fmaxf(mx1, __shfl_xor_sync(0xffffffffu, mx1, 1));
        mx1 = fmaxf(mx1, __shfl_xor_sync(0xffffffffu, mx1, 2));
        if (t == 0) { sWmax[nhalf * 64 + r0] = mx0; sWmax[nhalf * 64 + r1] = mx1; }
        __syncthreads();

        const float mn0 = fmaxf(sM[r0], fmaxf(sWmax[r0], sWmax[64 + r0]));
        const float mn1 = fmaxf(sM[r1], fmaxf(sWmax[r1], sWmax[64 + r1]));

        float sum0 = 0.f, sum1 = 0.f;
#pragma unroll
        for (int nt = 0; nt < 4; nt++) {
            s[nt][0] = __expf(s[nt][0] - mn0);
            s[nt][1] = __expf(s[nt][1] - mn0);
            s[nt][2] = __expf(s[nt][2] - mn1);
            s[nt][3] = __expf(s[nt][3] - mn1);
            sum0 += s[nt][0] + s[nt][1];
            sum1 += s[nt][2] + s[nt][3];
            const int coll = nhalf * 32 + nt * 8 + 2 * t;
            *(float2*)(sP + r0 * AT_LDP + coll) = make_float2(s[nt][0], s[nt][1]);
            *(float2*)(sP + r1 * AT_LDP + coll) = make_float2(s[nt][2], s[nt][3]);
        }
        sum0 += __shfl_xor_sync(0xffffffffu, sum0, 1);
        sum0 += __shfl_xor_sync(0xffffffffu, sum0, 2);
        sum1 += __shfl_xor_sync(0xffffffffu, sum1, 1);
        sum1 += __shfl_xor_sync(0xffffffffu, sum1, 2);
        if (t == 0) { sWsum[nhalf * 64 + r0] = sum0; sWsum[nhalf * 64 + r1] = sum1; }
        __syncthreads();

        if (tid < 64) {
            const float mo = sM[tid];
            const float mn = fmaxf(mo, fmaxf(sWmax[tid], sWmax[64 + tid]));
            const float sc = __expf(mo - mn);
            sM[tid] = mn;
            sL[tid] = sL[tid] * sc + sWsum[tid] + sWsum[64 + tid];
            sScale[tid] = sc;
        }
        __syncthreads();

        // rescale O acc
        const float sc0 = sScale[r0], sc1 = sScale[r1];
#pragma unroll
        for (int nt = 0; nt < 8; nt++) {
            o[nt][0] *= sc0; o[nt][1] *= sc0;
            o[nt][2] *= sc1; o[nt][3] *= sc1;
        }

        // ---- O += P @ V (warp patch 16 x 64) ----
        const float* pb = sP + r0 * AT_LDP + t;
#pragma unroll 2
        for (int kk = 0; kk < 64; kk += 8) {
            const unsigned int a0 = f2tf(pb[kk]);
            const unsigned int a1 = f2tf(pb[8 * AT_LDP + kk]);
            const unsigned int a2 = f2tf(pb[kk + 4]);
            const unsigned int a3 = f2tf(pb[8 * AT_LDP + kk + 4]);
#pragma unroll
            for (int nt = 0; nt < 8; nt++) {
                const int nc = nhalf * 64 + nt * 8 + g;
                const unsigned int b0 = f2tf(sV[(kk + t) * AT_LDV + nc]);
                const unsigned int b1 = f2tf(sV[(kk + t + 4) * AT_LDV + nc]);
                mma_tf32(o[nt], a0, a1, a2, a3, b0, b1);
            }
        }
    }

    // normalize + store
    const float il0 = 1.f / sL[r0];
    const float il1 = 1.f / sL[r1];
#pragma unroll
    for (int nt = 0; nt < 8; nt++) {
        const int col = h * D_V + nhalf * 64 + nt * 8 + 2 * t;
        *(float2*)(out + (size_t)(t0 + r0) * (NH * D_V) + col) =
            make_float2(o[nt][0] * il0, o[nt][1] * il0);
        *(float2*)(out + (size_t)(t0 + r1) * (NH * D_V) + col) =
            make_float2(o[nt][2] * il1, o[nt][3] * il1);
    }
}

// ---------------- launch ----------------
extern "C" void kernel_launch(void* const* d_in, const int* in_sizes, int n_in,
                              void* d_out, int out_size)
{
    const float* hidden    = (const float*)d_in[0];
    const int*   positions = (const int*)  d_in[1];
    const float* w_qkv_a   = (const float*)d_in[2];
    const float* gamma_q   = (const float*)d_in[3];
    const float* w_q_b     = (const float*)d_in[4];
    const float* gamma_kv  = (const float*)d_in[5];
    const float* w_kv_b    = (const float*)d_in[6];
    const float* w_o       = (const float*)d_in[7];
    float* out = (float*)d_out;

    float *qkv_a, *qn, *kvn, *qbuf, *kvbuf, *kpe, *attn;
    cudaGetSymbolAddress((void**)&qkv_a, g_qkv_a);
    cudaGetSymbolAddress((void**)&qn,    g_qn);
    cudaGetSymbolAddress((void**)&kvn,   g_kvn);
    cudaGetSymbolAddress((void**)&qbuf,  g_qbuf);
    cudaGetSymbolAddress((void**)&kvbuf, g_kvbuf);
    cudaGetSymbolAddress((void**)&kpe,   g_kpe);
    cudaGetSymbolAddress((void**)&attn,  g_attn);

    cudaFuncSetAttribute(tc_gemm, cudaFuncAttributeMaxDynamicSharedMemorySize, GEMM_SMEM_BYTES);
    const int attn_smem = AT_SMEM_FLOATS * (int)sizeof(float);
    cudaFuncSetAttribute(attn_tc_kernel, cudaFuncAttributeMaxDynamicSharedMemorySize, attn_smem);

    // 1) qkv_a = hidden @ w_qkv_a
    tc_gemm<<<dim3(QKV_A_N / GBN, T_TOK / GBM), 256, GEMM_SMEM_BYTES>>>(
        hidden, w_qkv_a, qkv_a, T_TOK, QKV_A_N, HID);

    // 2) RMSNorm
    rmsnorm_kernel<<<T_TOK, 256>>>(qkv_a, QKV_A_N, 0,      Q_LORA,  gamma_q,  qn);
    rmsnorm_kernel<<<T_TOK, 256>>>(qkv_a, QKV_A_N, Q_LORA, KV_LORA, gamma_kv, kvn);

    // 3) q = qn @ w_q_b
    tc_gemm<<<dim3((NH * D_QK) / GBN, T_TOK / GBM), 256, GEMM_SMEM_BYTES>>>(
        qn, w_q_b, qbuf, T_TOK, NH * D_QK, Q_LORA);

    // 4) kv = kvn @ w_kv_b
    tc_gemm<<<dim3((NH * 256) / GBN, T_TOK / GBM), 256, GEMM_SMEM_BYTES>>>(
        kvn, w_kv_b, kvbuf, T_TOK, NH * 256, KV_LORA);

    // 5) RoPE
    rope_kernel<<<T_TOK, 256>>>(qbuf, qkv_a, kpe, positions);

    // 6) attention
    attn_tc_kernel<<<dim3(T_TOK / 64, NH), 256, attn_smem>>>(qbuf, kvbuf, kpe, attn);

    // 7) out = attn @ w_o
    tc_gemm<<<dim3(HID / GBN, T_TOK / GBM), 256, GEMM_SMEM_BYTES>>>(
        attn, w_o, out, T_TOK, HID, NH * D_V);
}